// round 5
// baseline (speedup 1.0000x reference)
#include <cuda_runtime.h>
#include <cuda_bf16.h>
#include <stdint.h>

#define NNODES 100000
#define FDIM   64
#define EMAX   2000000   // reference uses E=1.6M; headroom

// ---------------------------------------------------------------------------
// Static device scratch (no allocation allowed anywhere)
// ---------------------------------------------------------------------------
__device__ __align__(16) float g_h[(size_t)NNODES * FDIM];    // 25.6 MB
__device__ __align__(16) float g_agg[(size_t)NNODES * FDIM];  // 25.6 MB
__device__ float g_dinv[NNODES];
__device__ int   g_degi[NNODES];
__device__ int   g_off[NNODES + 1];
__device__ int   g_cursor[NNODES];
__device__ __align__(8) int2 g_csr[EMAX];   // {src, bitcast(dinv[src])} 16 MB

// ---------------------------------------------------------------------------
__global__ void zero_deg_kernel() {
    int i = blockIdx.x * blockDim.x + threadIdx.x;
    if (i < NNODES) g_degi[i] = 0;
}

// histogram of in-edges (int atomics, exact)
__global__ void hist_kernel(const int* __restrict__ ei, long long E) {
    long long stride = (long long)gridDim.x * blockDim.x;
    for (long long e = (long long)blockIdx.x * blockDim.x + threadIdx.x;
         e < E; e += stride)
        atomicAdd(&g_degi[ei[E + e]], 1);
}

__global__ void dinv_kernel() {
    int i = blockIdx.x * blockDim.x + threadIdx.x;
    if (i < NNODES) g_dinv[i] = rsqrtf((float)g_degi[i] + 1.0f);
}

// ---------------------------------------------------------------------------
// Single-block exclusive scan of g_degi -> g_off (+ cursor copy)
// 1024 threads, each owns a contiguous chunk.
// ---------------------------------------------------------------------------
__global__ __launch_bounds__(1024) void scan_kernel() {
    const int T = 1024;
    const int chunk = (NNODES + T - 1) / T;   // 98
    __shared__ int part[T];
    const int tid = threadIdx.x;
    const int base = tid * chunk;
    const int lim  = min(base + chunk, NNODES);

    int sum = 0;
    for (int i = base; i < lim; i++) sum += g_degi[i];
    part[tid] = sum;
    __syncthreads();

    // Hillis-Steele inclusive scan
    for (int off = 1; off < T; off <<= 1) {
        int v = (tid >= off) ? part[tid - off] : 0;
        __syncthreads();
        part[tid] += v;
        __syncthreads();
    }

    int run = part[tid] - sum;   // exclusive prefix of this chunk
    for (int i = base; i < lim; i++) {
        g_off[i]    = run;
        g_cursor[i] = run;
        run += g_degi[i];
    }
    if (tid == T - 1) g_off[NNODES] = part[T - 1];
}

// ---------------------------------------------------------------------------
// CSR fill: csr[pos] = {src, dinv[src]}  (packed 8B write per edge)
// ---------------------------------------------------------------------------
__global__ void fill_kernel(const int* __restrict__ ei, long long E) {
    long long stride = (long long)gridDim.x * blockDim.x;
    for (long long e = (long long)blockIdx.x * blockDim.x + threadIdx.x;
         e < E; e += stride) {
        int s = ei[e];
        int d = ei[E + e];
        int pos = atomicAdd(&g_cursor[d], 1);
        g_csr[pos] = make_int2(s, __float_as_int(g_dinv[s]));
    }
}

// ---------------------------------------------------------------------------
// Aggregation (gather form): out[node] = dinv[node]*(sum_e dinv[src] x[src]
//                                          + dinv[node]*x[node])
// One warp per node; each lane owns 2 of the 64 features (float2).
// Row writes are streaming & exact-once: no atomics, no zero-init needed.
// ---------------------------------------------------------------------------
__global__ __launch_bounds__(256) void agg_kernel(
    const float* __restrict__ x, float* __restrict__ outv)
{
    const int lane = threadIdx.x & 31;
    const int gwarp = (blockIdx.x * blockDim.x + threadIdx.x) >> 5;
    const int nwarp = (gridDim.x * blockDim.x) >> 5;

    for (int node = gwarp; node < NNODES; node += nwarp) {
        const int beg = g_off[node];
        const int end = g_off[node + 1];

        float2 acc = make_float2(0.f, 0.f);

        for (int base = beg; base < end; base += 32) {
            const int cnt = min(32, end - base);
            int   s = 0;
            float w = 0.f;
            if (lane < cnt) {
                int2 ent = g_csr[base + lane];
                s = ent.x;
                w = __int_as_float(ent.y);
            }
#pragma unroll 4
            for (int j = 0; j < cnt; j++) {
                int   sj = __shfl_sync(0xffffffffu, s, j);
                float wj = __shfl_sync(0xffffffffu, w, j);
                float2 v = *reinterpret_cast<const float2*>(
                    x + (size_t)sj * FDIM + lane * 2);
                acc.x = fmaf(wj, v.x, acc.x);
                acc.y = fmaf(wj, v.y, acc.y);
            }
        }

        const float di = g_dinv[node];
        float2 sv = *reinterpret_cast<const float2*>(
            x + (size_t)node * FDIM + lane * 2);
        acc.x = fmaf(di, sv.x, acc.x) * di;
        acc.y = fmaf(di, sv.y, acc.y) * di;
        *reinterpret_cast<float2*>(outv + (size_t)node * FDIM + lane * 2) = acc;
    }
}

// ---------------------------------------------------------------------------
// GEMM: C[n,64] = relu(A[n,64] @ W[64,64] + b), fp32.
// 256 threads / 256 rows per block; 4 rows x 16 cols per thread.
// ---------------------------------------------------------------------------
#define ROWS_PER_BLK 256
#define A_STRIDE4    17

__global__ __launch_bounds__(256) void gemm64_kernel(
    const float* __restrict__ A, const float* __restrict__ W,
    const float* __restrict__ bias, float* __restrict__ C, int n_rows)
{
    extern __shared__ float smem[];
    float*  sW  = smem;                                        // 4096 floats
    float4* sA4 = reinterpret_cast<float4*>(smem + 64 * 64);   // 256*17 float4

    const int tid  = threadIdx.x;
    const int row0 = blockIdx.x * ROWS_PER_BLK;

    for (int i = tid; i < 1024; i += 256)
        reinterpret_cast<float4*>(sW)[i] =
            reinterpret_cast<const float4*>(W)[i];

    for (int i = tid; i < ROWS_PER_BLK * 16; i += 256) {
        int r  = i >> 4;
        int c4 = i & 15;
        int row = row0 + r;
        float4 v = make_float4(0.f, 0.f, 0.f, 0.f);
        if (row < n_rows)
            v = reinterpret_cast<const float4*>(A + (size_t)row * FDIM)[c4];
        sA4[r * A_STRIDE4 + c4] = v;
    }
    __syncthreads();

    const int rbase = (tid >> 2) * 4;
    const int cg    = (tid & 3) * 16;

    float acc[4][16];
#pragma unroll
    for (int r = 0; r < 4; r++)
#pragma unroll
        for (int i = 0; i < 16; i++) acc[r][i] = 0.f;

#pragma unroll
    for (int k4 = 0; k4 < 16; k4++) {
        float4 a[4];
#pragma unroll
        for (int r = 0; r < 4; r++)
            a[r] = sA4[(rbase + r) * A_STRIDE4 + k4];

#pragma unroll
        for (int kk = 0; kk < 4; kk++) {
            const float4* wr = reinterpret_cast<const float4*>(
                sW + (k4 * 4 + kk) * 64 + cg);
            float4 w0 = wr[0], w1 = wr[1], w2 = wr[2], w3 = wr[3];
#pragma unroll
            for (int r = 0; r < 4; r++) {
                float av = (&a[r].x)[kk];
                acc[r][0]  = fmaf(av, w0.x, acc[r][0]);
                acc[r][1]  = fmaf(av, w0.y, acc[r][1]);
                acc[r][2]  = fmaf(av, w0.z, acc[r][2]);
                acc[r][3]  = fmaf(av, w0.w, acc[r][3]);
                acc[r][4]  = fmaf(av, w1.x, acc[r][4]);
                acc[r][5]  = fmaf(av, w1.y, acc[r][5]);
                acc[r][6]  = fmaf(av, w1.z, acc[r][6]);
                acc[r][7]  = fmaf(av, w1.w, acc[r][7]);
                acc[r][8]  = fmaf(av, w2.x, acc[r][8]);
                acc[r][9]  = fmaf(av, w2.y, acc[r][9]);
                acc[r][10] = fmaf(av, w2.z, acc[r][10]);
                acc[r][11] = fmaf(av, w2.w, acc[r][11]);
                acc[r][12] = fmaf(av, w3.x, acc[r][12]);
                acc[r][13] = fmaf(av, w3.y, acc[r][13]);
                acc[r][14] = fmaf(av, w3.z, acc[r][14]);
                acc[r][15] = fmaf(av, w3.w, acc[r][15]);
            }
        }
    }

    float4 bv[4];
#pragma unroll
    for (int i = 0; i < 4; i++)
        bv[i] = reinterpret_cast<const float4*>(bias + cg)[i];

#pragma unroll
    for (int r = 0; r < 4; r++) {
        int row = row0 + rbase + r;
        if (row < n_rows) {
            float4* o = reinterpret_cast<float4*>(C + (size_t)row * FDIM + cg);
#pragma unroll
            for (int i = 0; i < 4; i++)
                o[i] = make_float4(
                    fmaxf(acc[r][4*i+0] + bv[i].x, 0.f),
                    fmaxf(acc[r][4*i+1] + bv[i].y, 0.f),
                    fmaxf(acc[r][4*i+2] + bv[i].z, 0.f),
                    fmaxf(acc[r][4*i+3] + bv[i].w, 0.f));
        }
    }
}

// ---------------------------------------------------------------------------
extern "C" void kernel_launch(void* const* d_in, const int* in_sizes, int n_in,
                              void* d_out, int out_size)
{
    const float* x  = (const float*)d_in[0];
    const int*   ei = (const int*)d_in[1];     // int32 (JAX x64 disabled)
    const float* W1 = (const float*)d_in[2];
    const float* b1 = (const float*)d_in[3];
    const float* W2 = (const float*)d_in[4];
    const float* b2 = (const float*)d_in[5];
    float* out = (float*)d_out;

    const long long E = (long long)in_sizes[1] / 2;

    float* g_h_ptr;   cudaGetSymbolAddress((void**)&g_h_ptr,   g_h);
    float* g_agg_ptr; cudaGetSymbolAddress((void**)&g_agg_ptr, g_agg);

    const int SMS = 148;
    dim3 blk(256);

    const int GEMM_SMEM = (64 * 64 + ROWS_PER_BLK * A_STRIDE4 * 4) * 4; // 84 KB
    static bool attr_done = false;
    if (!attr_done) {
        cudaFuncSetAttribute(gemm64_kernel,
            cudaFuncAttributeMaxDynamicSharedMemorySize, GEMM_SMEM);
        attr_done = true;
    }

    // ---- CSR build (once per launch, reused by both layers) ----
    zero_deg_kernel<<<(NNODES + 255) / 256, blk>>>();
    hist_kernel<<<SMS * 8, blk>>>(ei, E);
    dinv_kernel<<<(NNODES + 255) / 256, blk>>>();
    scan_kernel<<<1, 1024>>>();
    fill_kernel<<<SMS * 8, blk>>>(ei, E);

    const int gemm_grid = (NNODES + ROWS_PER_BLK - 1) / ROWS_PER_BLK;
    const int agg_grid  = SMS * 16;

    // ---- layer 1:  h1 = relu((Â x) W1 + b1) ----
    agg_kernel<<<agg_grid, blk>>>(x, g_agg_ptr);
    gemm64_kernel<<<gemm_grid, blk, GEMM_SMEM>>>(g_agg_ptr, W1, b1, g_h_ptr, NNODES);

    // ---- layer 2:  out = relu((Â h1) W2 + b2) ----
    agg_kernel<<<agg_grid, blk>>>(g_h_ptr, g_agg_ptr);
    gemm64_kernel<<<gemm_grid, blk, GEMM_SMEM>>>(g_agg_ptr, W2, b2, out, NNODES);
}

// round 6
// speedup vs baseline: 1.6438x; 1.6438x over previous
#include <cuda_runtime.h>
#include <cuda_bf16.h>
#include <stdint.h>

#define NNODES 100000
#define FDIM   64
#define EMAX   2000000   // reference uses E=1.6M; headroom

#define SCAN_BLK   1024
#define NSCANBLK   ((NNODES + SCAN_BLK - 1) / SCAN_BLK)   // 98

// ---------------------------------------------------------------------------
// Static device scratch (no allocation allowed anywhere)
// ---------------------------------------------------------------------------
__device__ __align__(16) float g_h[(size_t)NNODES * FDIM];    // 25.6 MB
__device__ __align__(16) float g_agg[(size_t)NNODES * FDIM];  // 25.6 MB
__device__ float g_dinv[NNODES];
__device__ int   g_degi[NNODES];
__device__ int   g_off[NNODES + 1];
__device__ int   g_cursor[NNODES];
__device__ int   g_bsum[NSCANBLK];
__device__ int   g_bpre[NSCANBLK];
__device__ __align__(8) int2 g_csr[EMAX];   // {src, bitcast(dinv[src])} 16 MB

// ---------------------------------------------------------------------------
__global__ void zero_deg_kernel() {
    int i = blockIdx.x * blockDim.x + threadIdx.x;
    if (i < NNODES) g_degi[i] = 0;
}

// histogram of in-edges (int atomics, exact)
__global__ void hist_kernel(const int* __restrict__ ei, long long E) {
    long long stride = (long long)gridDim.x * blockDim.x;
    for (long long e = (long long)blockIdx.x * blockDim.x + threadIdx.x;
         e < E; e += stride)
        atomicAdd(&g_degi[ei[E + e]], 1);
}

__global__ void dinv_kernel() {
    int i = blockIdx.x * blockDim.x + threadIdx.x;
    if (i < NNODES) g_dinv[i] = rsqrtf((float)g_degi[i] + 1.0f);
}

// ---------------------------------------------------------------------------
// Multi-block exclusive scan of g_degi -> g_off (+ cursor copy). 3 phases.
// ---------------------------------------------------------------------------
// Phase 1: per-block sums
__global__ __launch_bounds__(SCAN_BLK) void scan_reduce_kernel() {
    __shared__ int sh[SCAN_BLK / 32];
    int i = blockIdx.x * SCAN_BLK + threadIdx.x;
    int v = (i < NNODES) ? g_degi[i] : 0;
#pragma unroll
    for (int o = 16; o > 0; o >>= 1)
        v += __shfl_down_sync(0xffffffffu, v, o);
    if ((threadIdx.x & 31) == 0) sh[threadIdx.x >> 5] = v;
    __syncthreads();
    if (threadIdx.x < 32) {
        int w = (threadIdx.x < SCAN_BLK / 32) ? sh[threadIdx.x] : 0;
#pragma unroll
        for (int o = 16; o > 0; o >>= 1)
            w += __shfl_down_sync(0xffffffffu, w, o);
        if (threadIdx.x == 0) g_bsum[blockIdx.x] = w;
    }
}

// Phase 2: exclusive scan of the 98 block sums (1 block)
__global__ __launch_bounds__(128) void scan_bsum_kernel() {
    __shared__ int sh[128];
    int tid = threadIdx.x;
    int v = (tid < NSCANBLK) ? g_bsum[tid] : 0;
    sh[tid] = v;
    __syncthreads();
    for (int o = 1; o < 128; o <<= 1) {
        int t = (tid >= o) ? sh[tid - o] : 0;
        __syncthreads();
        sh[tid] += t;
        __syncthreads();
    }
    if (tid < NSCANBLK) g_bpre[tid] = sh[tid] - v;   // exclusive
    if (tid == 127) g_off[NNODES] = sh[127];         // total
}

// Phase 3: per-block exclusive scan + block prefix -> g_off, g_cursor
__global__ __launch_bounds__(SCAN_BLK) void scan_write_kernel() {
    __shared__ int sh[SCAN_BLK];
    int tid = threadIdx.x;
    int i = blockIdx.x * SCAN_BLK + tid;
    int v = (i < NNODES) ? g_degi[i] : 0;
    sh[tid] = v;
    __syncthreads();
    for (int o = 1; o < SCAN_BLK; o <<= 1) {
        int t = (tid >= o) ? sh[tid - o] : 0;
        __syncthreads();
        sh[tid] += t;
        __syncthreads();
    }
    if (i < NNODES) {
        int off = g_bpre[blockIdx.x] + sh[tid] - v;  // exclusive
        g_off[i]    = off;
        g_cursor[i] = off;
    }
}

// ---------------------------------------------------------------------------
// CSR fill: csr[pos] = {src, dinv[src]}  (packed 8B write per edge)
// ---------------------------------------------------------------------------
__global__ void fill_kernel(const int* __restrict__ ei, long long E) {
    long long stride = (long long)gridDim.x * blockDim.x;
    for (long long e = (long long)blockIdx.x * blockDim.x + threadIdx.x;
         e < E; e += stride) {
        int s = ei[e];
        int d = ei[E + e];
        int pos = atomicAdd(&g_cursor[d], 1);
        g_csr[pos] = make_int2(s, __float_as_int(g_dinv[s]));
    }
}

// ---------------------------------------------------------------------------
// Aggregation (gather form): out[node] = dinv[node]*(sum_e dinv[src] x[src]
//                                          + dinv[node]*x[node])
// One warp per node; each lane owns 2 of the 64 features (float2).
// Row writes are streaming & exact-once: no atomics, no zero-init needed.
// ---------------------------------------------------------------------------
__global__ __launch_bounds__(256) void agg_kernel(
    const float* __restrict__ x, float* __restrict__ outv)
{
    const int lane = threadIdx.x & 31;
    const int gwarp = (blockIdx.x * blockDim.x + threadIdx.x) >> 5;
    const int nwarp = (gridDim.x * blockDim.x) >> 5;

    for (int node = gwarp; node < NNODES; node += nwarp) {
        const int beg = g_off[node];
        const int end = g_off[node + 1];

        float2 acc = make_float2(0.f, 0.f);

        for (int base = beg; base < end; base += 32) {
            const int cnt = min(32, end - base);
            int   s = 0;
            float w = 0.f;
            if (lane < cnt) {
                int2 ent = g_csr[base + lane];
                s = ent.x;
                w = __int_as_float(ent.y);
            }
#pragma unroll 4
            for (int j = 0; j < cnt; j++) {
                int   sj = __shfl_sync(0xffffffffu, s, j);
                float wj = __shfl_sync(0xffffffffu, w, j);
                float2 v = *reinterpret_cast<const float2*>(
                    x + (size_t)sj * FDIM + lane * 2);
                acc.x = fmaf(wj, v.x, acc.x);
                acc.y = fmaf(wj, v.y, acc.y);
            }
        }

        const float di = g_dinv[node];
        float2 sv = *reinterpret_cast<const float2*>(
            x + (size_t)node * FDIM + lane * 2);
        acc.x = fmaf(di, sv.x, acc.x) * di;
        acc.y = fmaf(di, sv.y, acc.y) * di;
        *reinterpret_cast<float2*>(outv + (size_t)node * FDIM + lane * 2) = acc;
    }
}

// ---------------------------------------------------------------------------
// GEMM: C[n,64] = relu(A[n,64] @ W[64,64] + b), fp32.
// 256 threads / 256 rows per block; 4 rows x 16 cols per thread.
// ---------------------------------------------------------------------------
#define ROWS_PER_BLK 256
#define A_STRIDE4    17

__global__ __launch_bounds__(256) void gemm64_kernel(
    const float* __restrict__ A, const float* __restrict__ W,
    const float* __restrict__ bias, float* __restrict__ C, int n_rows)
{
    extern __shared__ float smem[];
    float*  sW  = smem;                                        // 4096 floats
    float4* sA4 = reinterpret_cast<float4*>(smem + 64 * 64);   // 256*17 float4

    const int tid  = threadIdx.x;
    const int row0 = blockIdx.x * ROWS_PER_BLK;

    for (int i = tid; i < 1024; i += 256)
        reinterpret_cast<float4*>(sW)[i] =
            reinterpret_cast<const float4*>(W)[i];

    for (int i = tid; i < ROWS_PER_BLK * 16; i += 256) {
        int r  = i >> 4;
        int c4 = i & 15;
        int row = row0 + r;
        float4 v = make_float4(0.f, 0.f, 0.f, 0.f);
        if (row < n_rows)
            v = reinterpret_cast<const float4*>(A + (size_t)row * FDIM)[c4];
        sA4[r * A_STRIDE4 + c4] = v;
    }
    __syncthreads();

    const int rbase = (tid >> 2) * 4;
    const int cg    = (tid & 3) * 16;

    float acc[4][16];
#pragma unroll
    for (int r = 0; r < 4; r++)
#pragma unroll
        for (int i = 0; i < 16; i++) acc[r][i] = 0.f;

#pragma unroll
    for (int k4 = 0; k4 < 16; k4++) {
        float4 a[4];
#pragma unroll
        for (int r = 0; r < 4; r++)
            a[r] = sA4[(rbase + r) * A_STRIDE4 + k4];

#pragma unroll
        for (int kk = 0; kk < 4; kk++) {
            const float4* wr = reinterpret_cast<const float4*>(
                sW + (k4 * 4 + kk) * 64 + cg);
            float4 w0 = wr[0], w1 = wr[1], w2 = wr[2], w3 = wr[3];
#pragma unroll
            for (int r = 0; r < 4; r++) {
                float av = (&a[r].x)[kk];
                acc[r][0]  = fmaf(av, w0.x, acc[r][0]);
                acc[r][1]  = fmaf(av, w0.y, acc[r][1]);
                acc[r][2]  = fmaf(av, w0.z, acc[r][2]);
                acc[r][3]  = fmaf(av, w0.w, acc[r][3]);
                acc[r][4]  = fmaf(av, w1.x, acc[r][4]);
                acc[r][5]  = fmaf(av, w1.y, acc[r][5]);
                acc[r][6]  = fmaf(av, w1.z, acc[r][6]);
                acc[r][7]  = fmaf(av, w1.w, acc[r][7]);
                acc[r][8]  = fmaf(av, w2.x, acc[r][8]);
                acc[r][9]  = fmaf(av, w2.y, acc[r][9]);
                acc[r][10] = fmaf(av, w2.z, acc[r][10]);
                acc[r][11] = fmaf(av, w2.w, acc[r][11]);
                acc[r][12] = fmaf(av, w3.x, acc[r][12]);
                acc[r][13] = fmaf(av, w3.y, acc[r][13]);
                acc[r][14] = fmaf(av, w3.z, acc[r][14]);
                acc[r][15] = fmaf(av, w3.w, acc[r][15]);
            }
        }
    }

    float4 bv[4];
#pragma unroll
    for (int i = 0; i < 4; i++)
        bv[i] = reinterpret_cast<const float4*>(bias + cg)[i];

#pragma unroll
    for (int r = 0; r < 4; r++) {
        int row = row0 + rbase + r;
        if (row < n_rows) {
            float4* o = reinterpret_cast<float4*>(C + (size_t)row * FDIM + cg);
#pragma unroll
            for (int i = 0; i < 4; i++)
                o[i] = make_float4(
                    fmaxf(acc[r][4*i+0] + bv[i].x, 0.f),
                    fmaxf(acc[r][4*i+1] + bv[i].y, 0.f),
                    fmaxf(acc[r][4*i+2] + bv[i].z, 0.f),
                    fmaxf(acc[r][4*i+3] + bv[i].w, 0.f));
        }
    }
}

// ---------------------------------------------------------------------------
extern "C" void kernel_launch(void* const* d_in, const int* in_sizes, int n_in,
                              void* d_out, int out_size)
{
    const float* x  = (const float*)d_in[0];
    const int*   ei = (const int*)d_in[1];     // int32 (JAX x64 disabled)
    const float* W1 = (const float*)d_in[2];
    const float* b1 = (const float*)d_in[3];
    const float* W2 = (const float*)d_in[4];
    const float* b2 = (const float*)d_in[5];
    float* out = (float*)d_out;

    const long long E = (long long)in_sizes[1] / 2;

    float* g_h_ptr;   cudaGetSymbolAddress((void**)&g_h_ptr,   g_h);
    float* g_agg_ptr; cudaGetSymbolAddress((void**)&g_agg_ptr, g_agg);

    const int SMS = 148;
    dim3 blk(256);

    const int GEMM_SMEM = (64 * 64 + ROWS_PER_BLK * A_STRIDE4 * 4) * 4; // 84 KB
    static bool attr_done = false;
    if (!attr_done) {
        cudaFuncSetAttribute(gemm64_kernel,
            cudaFuncAttributeMaxDynamicSharedMemorySize, GEMM_SMEM);
        attr_done = true;
    }

    // ---- CSR build (once per launch, reused by both layers) ----
    zero_deg_kernel<<<(NNODES + 255) / 256, blk>>>();
    hist_kernel<<<SMS * 8, blk>>>(ei, E);
    dinv_kernel<<<(NNODES + 255) / 256, blk>>>();
    scan_reduce_kernel<<<NSCANBLK, SCAN_BLK>>>();
    scan_bsum_kernel<<<1, 128>>>();
    scan_write_kernel<<<NSCANBLK, SCAN_BLK>>>();
    fill_kernel<<<SMS * 8, blk>>>(ei, E);

    const int gemm_grid = (NNODES + ROWS_PER_BLK - 1) / ROWS_PER_BLK;
    const int agg_grid  = SMS * 16;

    // ---- layer 1:  h1 = relu((Â x) W1 + b1) ----
    agg_kernel<<<agg_grid, blk>>>(x, g_agg_ptr);
    gemm64_kernel<<<gemm_grid, blk, GEMM_SMEM>>>(g_agg_ptr, W1, b1, g_h_ptr, NNODES);

    // ---- layer 2:  out = relu((Â h1) W2 + b2) ----
    agg_kernel<<<agg_grid, blk>>>(g_h_ptr, g_agg_ptr);
    gemm64_kernel<<<gemm_grid, blk, GEMM_SMEM>>>(g_agg_ptr, W2, b2, out, NNODES);
}